// round 1
// baseline (speedup 1.0000x reference)
#include <cuda_runtime.h>
#include <math.h>

#define B_   2
#define S_   2048
#define H_   3072
#define NH   32
#define NKV  8
#define HD   96
#define QKV_W (NH*HD + 2*NKV*HD)   // 4608
#define M_   (B_*S_)               // 4096

// Scratch (device globals: allocation-free rule)
__device__ float g_qkv[(size_t)M_ * QKV_W];   // [4096, 4608]  q | k | v
__device__ float g_attn[(size_t)M_ * H_];     // [4096, 3072]  attention output

// ---------------------------------------------------------------------------
// SGEMM NT: C[m,n] = sum_k A[m,k] * B[n,k].  A:[M,K] B:[N,K] row-major.
// 128x128x16 tiles, 256 threads, 8x8 register microtile.
// ---------------------------------------------------------------------------
__global__ __launch_bounds__(256, 2) void sgemm_nt(
    const float* __restrict__ A, const float* __restrict__ B, float* __restrict__ C,
    int M, int N, int K)
{
    __shared__ float As[16][132];   // [k][m], padded to cut store conflicts
    __shared__ float Bs[16][132];   // [k][n]

    const int tid  = threadIdx.x;
    const int bm   = blockIdx.y * 128;
    const int bn   = blockIdx.x * 128;
    const int lrow = tid >> 2;           // 0..63
    const int lcol = (tid & 3) << 2;     // 0,4,8,12
    const int ty   = tid >> 4;           // 0..15
    const int tx   = tid & 15;           // 0..15

    const float* Ap0 = A + (bm + lrow) * K + lcol;
    const float* Ap1 = Ap0 + 64 * K;
    const float* Bp0 = B + (bn + lrow) * K + lcol;
    const float* Bp1 = Bp0 + 64 * K;

    float acc[8][8];
#pragma unroll
    for (int i = 0; i < 8; i++)
#pragma unroll
        for (int j = 0; j < 8; j++) acc[i][j] = 0.f;

    for (int k0 = 0; k0 < K; k0 += 16) {
        float4 a0 = *(const float4*)(Ap0 + k0);
        float4 a1 = *(const float4*)(Ap1 + k0);
        float4 b0 = *(const float4*)(Bp0 + k0);
        float4 b1 = *(const float4*)(Bp1 + k0);
        __syncthreads();
        As[lcol+0][lrow]    = a0.x; As[lcol+1][lrow]    = a0.y;
        As[lcol+2][lrow]    = a0.z; As[lcol+3][lrow]    = a0.w;
        As[lcol+0][lrow+64] = a1.x; As[lcol+1][lrow+64] = a1.y;
        As[lcol+2][lrow+64] = a1.z; As[lcol+3][lrow+64] = a1.w;
        Bs[lcol+0][lrow]    = b0.x; Bs[lcol+1][lrow]    = b0.y;
        Bs[lcol+2][lrow]    = b0.z; Bs[lcol+3][lrow]    = b0.w;
        Bs[lcol+0][lrow+64] = b1.x; Bs[lcol+1][lrow+64] = b1.y;
        Bs[lcol+2][lrow+64] = b1.z; Bs[lcol+3][lrow+64] = b1.w;
        __syncthreads();
#pragma unroll
        for (int kk = 0; kk < 16; kk++) {
            float a[8], b[8];
            *(float4*)(a)     = *(const float4*)(&As[kk][ty*8]);
            *(float4*)(a + 4) = *(const float4*)(&As[kk][ty*8 + 4]);
            *(float4*)(b)     = *(const float4*)(&Bs[kk][tx*8]);
            *(float4*)(b + 4) = *(const float4*)(&Bs[kk][tx*8 + 4]);
#pragma unroll
            for (int i = 0; i < 8; i++)
#pragma unroll
                for (int j = 0; j < 8; j++)
                    acc[i][j] += a[i] * b[j];
        }
    }

#pragma unroll
    for (int i = 0; i < 8; i++) {
        float* Crow = C + (bm + ty*8 + i) * N + bn + tx*8;
        *(float4*)(Crow)     = make_float4(acc[i][0], acc[i][1], acc[i][2], acc[i][3]);
        *(float4*)(Crow + 4) = make_float4(acc[i][4], acc[i][5], acc[i][6], acc[i][7]);
    }
}

// ---------------------------------------------------------------------------
// RoPE on q (32 heads) and k (8 heads), in place in g_qkv.
// position_ids == arange(S) broadcast over B (by construction of the problem).
// ---------------------------------------------------------------------------
__global__ void rope_kernel(float* __restrict__ qkv)
{
    const int total = B_ * S_ * (NH + NKV) * (HD / 2);
    int i = blockIdx.x * blockDim.x + threadIdx.x;
    if (i >= total) return;
    int d    = i % (HD/2);              // 0..47
    int t    = i / (HD/2);
    int head = t % (NH + NKV);          // 0..39 (q heads then k heads, contiguous)
    int bs   = t / (NH + NKV);          // 0..4095
    int s    = bs % S_;                 // position

    float inv = expf(-(float)d * (logf(10000.0f) / 48.0f));
    float ang = (float)s * inv;
    float sn, cs;
    sincosf(ang, &sn, &cs);

    float* base = qkv + (size_t)bs * QKV_W + head * HD;
    float x1 = base[d];
    float x2 = base[d + 48];
    base[d]      = x1 * cs - x2 * sn;
    base[d + 48] = x2 * cs + x1 * sn;
}

// ---------------------------------------------------------------------------
// Flash attention, fp32. One block per (b, h, 64-query tile). 256 threads.
// Online softmax across 64-key tiles; causal skip of upper tiles.
// ---------------------------------------------------------------------------
#define SD 65   // padded score-row stride

__global__ __launch_bounds__(256, 2) void attn_kernel(
    const float* __restrict__ qkv, float* __restrict__ attn)
{
    extern __shared__ float sm[];
    float* Qs   = sm;                 // [96][64], d-major
    float* Ks   = Qs + 96*64;         // [96][64], d-major
    float* Vs   = Ks + 96*64;         // [64][96], j-major
    float* Ss   = Vs + 64*96;         // [64][SD]
    float* mrow = Ss + 64*SD;         // [64]
    float* lrow = mrow + 64;          // [64]
    float* alph = lrow + 64;          // [64]

    const int tid = threadIdx.x;
    const int qt  = blockIdx.x;            // 0..31
    const int bh  = blockIdx.y;            // 0..63
    const int b   = bh >> 5;
    const int h   = bh & 31;
    const int kvh = h >> 2;
    const int q0  = qt * 64;
    const float scale = 0.10206207261596577f;   // 1/sqrt(96)

    const float* qbase = qkv + (b * S_) * QKV_W + h * HD;
    const float* kbase = qkv + (b * S_) * QKV_W + NH*HD + kvh * HD;
    const float* vbase = kbase + NKV*HD;

    // Load Q tile transposed: Qs[d][qi]
#pragma unroll
    for (int u = 0; u < 6; u++) {
        int f  = tid + u * 256;            // 0..1535
        int r  = f / 24;                   // query row 0..63
        int d4 = (f % 24) * 4;
        float4 v = *(const float4*)(qbase + (q0 + r) * QKV_W + d4);
        Qs[(d4+0)*64 + r] = v.x; Qs[(d4+1)*64 + r] = v.y;
        Qs[(d4+2)*64 + r] = v.z; Qs[(d4+3)*64 + r] = v.w;
    }
    if (tid < 64) { mrow[tid] = -1e30f; lrow[tid] = 0.f; }

    const int ty = tid >> 4, tx = tid & 15;
    float oacc[4][6];
#pragma unroll
    for (int i = 0; i < 4; i++)
#pragma unroll
        for (int j = 0; j < 6; j++) oacc[i][j] = 0.f;

    __syncthreads();

    for (int kt = 0; kt <= qt; kt++) {
        const int k0 = kt * 64;
        // K/V tile load (Ks transposed, Vs natural)
#pragma unroll
        for (int u = 0; u < 6; u++) {
            int f  = tid + u * 256;
            int r  = f / 24;
            int d4 = (f % 24) * 4;
            float4 kv = *(const float4*)(kbase + (k0 + r) * QKV_W + d4);
            float4 vv = *(const float4*)(vbase + (k0 + r) * QKV_W + d4);
            Ks[(d4+0)*64 + r] = kv.x; Ks[(d4+1)*64 + r] = kv.y;
            Ks[(d4+2)*64 + r] = kv.z; Ks[(d4+3)*64 + r] = kv.w;
            *(float4*)(Vs + r*96 + d4) = vv;
        }
        __syncthreads();

        // Scores: S = scale * Q K^T (4x4 per thread)
        float sacc[4][4];
#pragma unroll
        for (int i = 0; i < 4; i++)
#pragma unroll
            for (int j = 0; j < 4; j++) sacc[i][j] = 0.f;
#pragma unroll 8
        for (int d = 0; d < 96; d++) {
            float4 aq = *(const float4*)(Qs + d*64 + ty*4);
            float4 bk = *(const float4*)(Ks + d*64 + tx*4);
            float a[4] = {aq.x, aq.y, aq.z, aq.w};
            float c[4] = {bk.x, bk.y, bk.z, bk.w};
#pragma unroll
            for (int i = 0; i < 4; i++)
#pragma unroll
                for (int j = 0; j < 4; j++)
                    sacc[i][j] += a[i] * c[j];
        }
        const bool diag = (kt == qt);
#pragma unroll
        for (int i = 0; i < 4; i++)
#pragma unroll
            for (int j = 0; j < 4; j++) {
                int qi = ty*4 + i, kj = tx*4 + j;
                float s = sacc[i][j] * scale;
                if (diag && kj > qi) s = -1e30f;
                Ss[qi*SD + kj] = s;
            }
        __syncthreads();

        // Online softmax per query row (threads 0..63)
        if (tid < 64) {
            const int q = tid;
            float m_old = mrow[q];
            float mx = m_old;
#pragma unroll 8
            for (int j = 0; j < 64; j++) mx = fmaxf(mx, Ss[q*SD + j]);
            float sum = 0.f;
#pragma unroll 8
            for (int j = 0; j < 64; j++) {
                float p = __expf(Ss[q*SD + j] - mx);
                Ss[q*SD + j] = p;
                sum += p;
            }
            float al = __expf(m_old - mx);
            alph[q] = al;
            lrow[q] = lrow[q] * al + sum;
            mrow[q] = mx;
        }
        __syncthreads();

        // O = alpha*O + P @ V   (4 queries x 6 dims per thread)
        float al[4];
#pragma unroll
        for (int i = 0; i < 4; i++) al[i] = alph[ty*4 + i];
#pragma unroll
        for (int i = 0; i < 4; i++)
#pragma unroll
            for (int jd = 0; jd < 6; jd++) oacc[i][jd] *= al[i];
#pragma unroll 4
        for (int j = 0; j < 64; j++) {
            float p[4];
#pragma unroll
            for (int i = 0; i < 4; i++) p[i] = Ss[(ty*4 + i)*SD + j];
            float2 v0 = *(const float2*)(Vs + j*96 + tx*6);
            float2 v1 = *(const float2*)(Vs + j*96 + tx*6 + 2);
            float2 v2 = *(const float2*)(Vs + j*96 + tx*6 + 4);
            float v[6] = {v0.x, v0.y, v1.x, v1.y, v2.x, v2.y};
#pragma unroll
            for (int i = 0; i < 4; i++)
#pragma unroll
                for (int jd = 0; jd < 6; jd++)
                    oacc[i][jd] += p[i] * v[jd];
        }
        __syncthreads();
    }

    // Epilogue: normalize and store to g_attn[b, q, h*96 + d]
#pragma unroll
    for (int i = 0; i < 4; i++) {
        int q = ty*4 + i;
        float inv_l = 1.f / lrow[q];
        float* orow = attn + (b*S_ + q0 + q) * H_ + h*HD + tx*6;
        *(float2*)(orow)     = make_float2(oacc[i][0]*inv_l, oacc[i][1]*inv_l);
        *(float2*)(orow + 2) = make_float2(oacc[i][2]*inv_l, oacc[i][3]*inv_l);
        *(float2*)(orow + 4) = make_float2(oacc[i][4]*inv_l, oacc[i][5]*inv_l);
    }
}

// ---------------------------------------------------------------------------

extern "C" void kernel_launch(void* const* d_in, const int* in_sizes, int n_in,
                              void* d_out, int out_size)
{
    const float* hidden = (const float*)d_in[0];
    // d_in[1] = position_ids (arange(S) broadcast; positions derived from index)
    const float* w_qkv  = (const float*)d_in[2];
    const float* w_o    = (const float*)d_in[3];
    float* out = (float*)d_out;

    float *qkv = nullptr, *attn = nullptr;
    cudaGetSymbolAddress((void**)&qkv,  g_qkv);
    cudaGetSymbolAddress((void**)&attn, g_attn);

    // 1) QKV projection: [4096,3072] @ [4608,3072]^T -> [4096,4608]
    sgemm_nt<<<dim3(QKV_W/128, M_/128), 256>>>(hidden, w_qkv, qkv, M_, QKV_W, H_);

    // 2) RoPE on q,k in place
    {
        int total = B_ * S_ * (NH + NKV) * (HD/2);
        rope_kernel<<<(total + 255)/256, 256>>>(qkv);
    }

    // 3) Causal GQA flash attention
    {
        const int smem = (96*64*2 + 64*96 + 64*SD + 3*64) * (int)sizeof(float);
        cudaFuncSetAttribute(attn_kernel, cudaFuncAttributeMaxDynamicSharedMemorySize, smem);
        attn_kernel<<<dim3(S_/64, B_*NH), 256, smem>>>(qkv, attn);
    }

    // 4) Output projection: [4096,3072] @ [3072,3072]^T -> [4096,3072]
    sgemm_nt<<<dim3(H_/128, M_/128), 256>>>(attn, w_o, out, M_, H_, H_);
}

// round 3
// speedup vs baseline: 1.6630x; 1.6630x over previous
#include <cuda_runtime.h>
#include <cuda_bf16.h>
#include <math.h>
#include <stdint.h>

#define B_   2
#define S_   2048
#define H_   3072
#define NH   32
#define NKV  8
#define HD   96
#define QKV_W (NH*HD + 2*NKV*HD)   // 4608
#define M_   (B_*S_)               // 4096

// ---------------- scratch (device globals: allocation-free rule) -----------
__device__ float g_qkv[(size_t)M_ * QKV_W];
__device__ float g_attn[(size_t)M_ * H_];
__device__ __nv_bfloat16 g_h_hi[(size_t)M_ * H_],     g_h_lo[(size_t)M_ * H_];
__device__ __nv_bfloat16 g_wq_hi[(size_t)QKV_W * H_], g_wq_lo[(size_t)QKV_W * H_];
__device__ __nv_bfloat16 g_wo_hi[(size_t)H_ * H_],    g_wo_lo[(size_t)H_ * H_];
__device__ __nv_bfloat16 g_a_hi[(size_t)M_ * H_],     g_a_lo[(size_t)M_ * H_];

// ---------------- base-target PTX helpers (no tcgen05 / no 'a' features) ---
__device__ __forceinline__ void cp_async16(uint32_t dst, const void* src) {
    asm volatile("cp.async.cg.shared.global [%0], [%1], 16;"
                 :: "r"(dst), "l"(src) : "memory");
}
#define CP_COMMIT() asm volatile("cp.async.commit_group;" ::: "memory")
#define CP_WAIT(n)  asm volatile("cp.async.wait_group %0;" :: "n"(n) : "memory")

__device__ __forceinline__ void ldsm4(uint32_t& r0, uint32_t& r1, uint32_t& r2,
                                      uint32_t& r3, uint32_t addr) {
    asm volatile("ldmatrix.sync.aligned.m8n8.x4.shared.b16 {%0,%1,%2,%3}, [%4];"
                 : "=r"(r0), "=r"(r1), "=r"(r2), "=r"(r3) : "r"(addr));
}

__device__ __forceinline__ void mma16816(float* c, uint32_t a0, uint32_t a1,
                                         uint32_t a2, uint32_t a3,
                                         uint32_t b0, uint32_t b1) {
    asm volatile(
        "mma.sync.aligned.m16n8k16.row.col.f32.bf16.bf16.f32 "
        "{%0,%1,%2,%3}, {%4,%5,%6,%7}, {%8,%9}, {%0,%1,%2,%3};"
        : "+f"(c[0]), "+f"(c[1]), "+f"(c[2]), "+f"(c[3])
        : "r"(a0), "r"(a1), "r"(a2), "r"(a3), "r"(b0), "r"(b1));
}

// ---------------------------------------------------------------------------
// fp32 -> (bf16 hi, bf16 lo) split
// ---------------------------------------------------------------------------
__global__ void split_f32(const float* __restrict__ x,
                          __nv_bfloat16* __restrict__ hi,
                          __nv_bfloat16* __restrict__ lo, int n4)
{
    int i = blockIdx.x * blockDim.x + threadIdx.x;
    if (i >= n4) return;
    float4 v = ((const float4*)x)[i];
    __nv_bfloat16 h0 = __float2bfloat16_rn(v.x);
    __nv_bfloat16 h1 = __float2bfloat16_rn(v.y);
    __nv_bfloat16 h2 = __float2bfloat16_rn(v.z);
    __nv_bfloat16 h3 = __float2bfloat16_rn(v.w);
    __nv_bfloat16 l0 = __float2bfloat16_rn(v.x - __bfloat162float(h0));
    __nv_bfloat16 l1 = __float2bfloat16_rn(v.y - __bfloat162float(h1));
    __nv_bfloat16 l2 = __float2bfloat16_rn(v.z - __bfloat162float(h2));
    __nv_bfloat16 l3 = __float2bfloat16_rn(v.w - __bfloat162float(h3));
    ((__nv_bfloat162*)hi)[2*i]   = __nv_bfloat162(h0, h1);
    ((__nv_bfloat162*)hi)[2*i+1] = __nv_bfloat162(h2, h3);
    ((__nv_bfloat162*)lo)[2*i]   = __nv_bfloat162(l0, l1);
    ((__nv_bfloat162*)lo)[2*i+1] = __nv_bfloat162(l2, l3);
}

// ---------------------------------------------------------------------------
// 3xBF16 mma.sync GEMM (NT): C[m,n] = sum_k A[m,k]*B[n,k], fp32 out.
// CTA tile 128x128, BK=32, 8 warps in 2x4 (warp tile 64x32).
// smem per buffer: Ahi|Alo|Bhi|Blo, each [128][40] bf16 (pad 8 -> conflict-free
// ldmatrix). Double-buffered cp.async.
// ---------------------------------------------------------------------------
#define BK      32
#define LDS_    40                    // padded row length (bf16)
#define PLANE_B (128 * LDS_ * 2)      // 10240 bytes per plane
#define BUF_B   (4 * PLANE_B)         // 40960 per buffer
#define GEMM_SMEM (2 * BUF_B)         // 81920

__global__ __launch_bounds__(256, 1) void gemm_3xbf16(
    const __nv_bfloat16* __restrict__ Ahi, const __nv_bfloat16* __restrict__ Alo,
    const __nv_bfloat16* __restrict__ Bhi, const __nv_bfloat16* __restrict__ Blo,
    float* __restrict__ C, int N, int K)
{
    extern __shared__ __align__(128) char smc[];
    const uint32_t sbase = (uint32_t)__cvta_generic_to_shared(smc);
    const int tid  = threadIdx.x;
    const int warp = tid >> 5, lane = tid & 31;
    const int bm = blockIdx.y * 128, bn = blockIdx.x * 128;
    const int wm = (warp >> 2) * 64;      // 0 or 64
    const int wn = (warp & 3) * 32;       // 0,32,64,96

    const __nv_bfloat16* srcs[4] = {
        Ahi + (size_t)bm * K, Alo + (size_t)bm * K,
        Bhi + (size_t)bn * K, Blo + (size_t)bn * K };

    const int nch = K / BK;

    // loader: 4 planes x 128 rows x 2 x 16B = 2048 cp.asyncs, 8 per thread
    auto load_chunk = [&](int kc, int bb) {
        uint32_t sb = sbase + bb * BUF_B;
        #pragma unroll
        for (int p = 0; p < 4; p++) {
            const __nv_bfloat16* sp = srcs[p] + kc * BK;
            uint32_t pb = sb + p * PLANE_B;
            #pragma unroll
            for (int t = 0; t < 2; t++) {
                int f = tid + t * 256;        // 0..511
                int r = f >> 2, j = f & 3;    // row 0..127, 16B chunk 0..3
                cp_async16(pb + r * (LDS_ * 2) + j * 16,
                           sp + (size_t)r * K + j * 8);
            }
        }
        CP_COMMIT();
    };

    float c[4][4][4];
    #pragma unroll
    for (int i = 0; i < 4; i++)
        #pragma unroll
        for (int j = 0; j < 4; j++)
            #pragma unroll
            for (int q = 0; q < 4; q++) c[i][j][q] = 0.f;

    load_chunk(0, 0);

    // per-lane ldmatrix address components
    const int arow = lane & 15;            // A: row within 16
    const int ak8  = (lane >> 4) * 8;      // A: k-half select
    const int brow = (lane & 7) + ((lane >> 4) << 3);  // B: row within 16 (tile pair)
    const int bk8  = ((lane >> 3) & 1) * 8;            // B: k-half select

    #pragma unroll 1
    for (int kc = 0; kc < nch; kc++) {
        const int bb = kc & 1;
        if (kc + 1 < nch) { load_chunk(kc + 1, (kc + 1) & 1); CP_WAIT(1); }
        else              { CP_WAIT(0); }
        __syncthreads();

        const uint32_t sAh = sbase + bb * BUF_B;
        const uint32_t sAl = sAh + PLANE_B;
        const uint32_t sBh = sAh + 2 * PLANE_B;
        const uint32_t sBl = sAh + 3 * PLANE_B;

        #pragma unroll
        for (int ks = 0; ks < 2; ks++) {
            const int k0 = ks * 16;
            uint32_t ah[4][4], al[4][4], bh[4][2], bl[4][2];
            #pragma unroll
            for (int ti = 0; ti < 4; ti++) {
                uint32_t off = (uint32_t)((wm + ti*16 + arow) * LDS_ + k0 + ak8) * 2;
                ldsm4(ah[ti][0], ah[ti][1], ah[ti][2], ah[ti][3], sAh + off);
                ldsm4(al[ti][0], al[ti][1], al[ti][2], al[ti][3], sAl + off);
            }
            #pragma unroll
            for (int tp = 0; tp < 2; tp++) {   // each covers 2 n8 tiles
                uint32_t off = (uint32_t)((wn + tp*16 + brow) * LDS_ + k0 + bk8) * 2;
                ldsm4(bh[tp*2][0], bh[tp*2][1], bh[tp*2+1][0], bh[tp*2+1][1], sBh + off);
                ldsm4(bl[tp*2][0], bl[tp*2][1], bl[tp*2+1][0], bl[tp*2+1][1], sBl + off);
            }
            #pragma unroll
            for (int ti = 0; ti < 4; ti++)
                #pragma unroll
                for (int tj = 0; tj < 4; tj++) {
                    mma16816(c[ti][tj], ah[ti][0], ah[ti][1], ah[ti][2], ah[ti][3],
                             bh[tj][0], bh[tj][1]);
                    mma16816(c[ti][tj], ah[ti][0], ah[ti][1], ah[ti][2], ah[ti][3],
                             bl[tj][0], bl[tj][1]);
                    mma16816(c[ti][tj], al[ti][0], al[ti][1], al[ti][2], al[ti][3],
                             bh[tj][0], bh[tj][1]);
                }
        }
        __syncthreads();
    }

    // epilogue: direct stores
    const int cr = lane >> 2, cc = (lane & 3) * 2;
    #pragma unroll
    for (int ti = 0; ti < 4; ti++) {
        #pragma unroll
        for (int tj = 0; tj < 4; tj++) {
            int r0 = bm + wm + ti*16 + cr;
            int col = bn + wn + tj*8 + cc;
            *(float2*)(C + (size_t)r0 * N + col)       = make_float2(c[ti][tj][0], c[ti][tj][1]);
            *(float2*)(C + (size_t)(r0 + 8) * N + col) = make_float2(c[ti][tj][2], c[ti][tj][3]);
        }
    }
}

// ---------------------------------------------------------------------------
// RoPE on q (32 heads) and k (8 heads), in place. positions = arange(S).
// ---------------------------------------------------------------------------
__global__ void rope_kernel(float* __restrict__ qkv)
{
    const int total = B_ * S_ * (NH + NKV) * (HD / 2);
    int i = blockIdx.x * blockDim.x + threadIdx.x;
    if (i >= total) return;
    int d    = i % (HD/2);
    int t    = i / (HD/2);
    int head = t % (NH + NKV);
    int bs   = t / (NH + NKV);
    int s    = bs % S_;

    float inv = expf(-(float)d * (logf(10000.0f) / 48.0f));
    float ang = (float)s * inv;
    float sn, cs;
    sincosf(ang, &sn, &cs);

    float* base = qkv + (size_t)bs * QKV_W + head * HD;
    float x1 = base[d];
    float x2 = base[d + 48];
    base[d]      = x1 * cs - x2 * sn;
    base[d + 48] = x2 * cs + x1 * sn;
}

// ---------------------------------------------------------------------------
// Flash attention, fp32 (round-1 kernel, unchanged).
// ---------------------------------------------------------------------------
#define SD 65

__global__ __launch_bounds__(256, 2) void attn_kernel(
    const float* __restrict__ qkv, float* __restrict__ attn)
{
    extern __shared__ float sm[];
    float* Qs   = sm;
    float* Ks   = Qs + 96*64;
    float* Vs   = Ks + 96*64;
    float* Ss   = Vs + 64*96;
    float* mrow = Ss + 64*SD;
    float* lrow = mrow + 64;
    float* alph = lrow + 64;

    const int tid = threadIdx.x;
    const int qt  = blockIdx.x;
    const int bh  = blockIdx.y;
    const int b   = bh >> 5;
    const int h   = bh & 31;
    const int kvh = h >> 2;
    const int q0  = qt * 64;
    const float scale = 0.10206207261596577f;

    const float* qbase = qkv + (b * S_) * QKV_W + h * HD;
    const float* kbase = qkv + (b * S_) * QKV_W + NH*HD + kvh * HD;
    const float* vbase = kbase + NKV*HD;

#pragma unroll
    for (int u = 0; u < 6; u++) {
        int f  = tid + u * 256;
        int r  = f / 24;
        int d4 = (f % 24) * 4;
        float4 v = *(const float4*)(qbase + (size_t)(q0 + r) * QKV_W + d4);
        Qs[(d4+0)*64 + r] = v.x; Qs[(d4+1)*64 + r] = v.y;
        Qs[(d4+2)*64 + r] = v.z; Qs[(d4+3)*64 + r] = v.w;
    }
    if (tid < 64) { mrow[tid] = -1e30f; lrow[tid] = 0.f; }

    const int ty = tid >> 4, tx = tid & 15;
    float oacc[4][6];
#pragma unroll
    for (int i = 0; i < 4; i++)
#pragma unroll
        for (int j = 0; j < 6; j++) oacc[i][j] = 0.f;

    __syncthreads();

    for (int kt = 0; kt <= qt; kt++) {
        const int k0 = kt * 64;
#pragma unroll
        for (int u = 0; u < 6; u++) {
            int f  = tid + u * 256;
            int r  = f / 24;
            int d4 = (f % 24) * 4;
            float4 kv = *(const float4*)(kbase + (size_t)(k0 + r) * QKV_W + d4);
            float4 vv = *(const float4*)(vbase + (size_t)(k0 + r) * QKV_W + d4);
            Ks[(d4+0)*64 + r] = kv.x; Ks[(d4+1)*64 + r] = kv.y;
            Ks[(d4+2)*64 + r] = kv.z; Ks[(d4+3)*64 + r] = kv.w;
            *(float4*)(Vs + r*96 + d4) = vv;
        }
        __syncthreads();

        float sacc[4][4];
#pragma unroll
        for (int i = 0; i < 4; i++)
#pragma unroll
            for (int j = 0; j < 4; j++) sacc[i][j] = 0.f;
#pragma unroll 8
        for (int d = 0; d < 96; d++) {
            float4 aq = *(const float4*)(Qs + d*64 + ty*4);
            float4 bk = *(const float4*)(Ks + d*64 + tx*4);
            float a[4] = {aq.x, aq.y, aq.z, aq.w};
            float cc[4] = {bk.x, bk.y, bk.z, bk.w};
#pragma unroll
            for (int i = 0; i < 4; i++)
#pragma unroll
                for (int j = 0; j < 4; j++)
                    sacc[i][j] += a[i] * cc[j];
        }
        const bool diag = (kt == qt);
#pragma unroll
        for (int i = 0; i < 4; i++)
#pragma unroll
            for (int j = 0; j < 4; j++) {
                int qi = ty*4 + i, kj = tx*4 + j;
                float s = sacc[i][j] * scale;
                if (diag && kj > qi) s = -1e30f;
                Ss[qi*SD + kj] = s;
            }
        __syncthreads();

        if (tid < 64) {
            const int q = tid;
            float m_old = mrow[q];
            float mx = m_old;
#pragma unroll 8
            for (int j = 0; j < 64; j++) mx = fmaxf(mx, Ss[q*SD + j]);
            float sum = 0.f;
#pragma unroll 8
            for (int j = 0; j < 64; j++) {
                float p = __expf(Ss[q*SD + j] - mx);
                Ss[q*SD + j] = p;
                sum += p;
            }
            float al = __expf(m_old - mx);
            alph[q] = al;
            lrow[q] = lrow[q] * al + sum;
            mrow[q] = mx;
        }
        __syncthreads();

        float al[4];
#pragma unroll
        for (int i = 0; i < 4; i++) al[i] = alph[ty*4 + i];
#pragma unroll
        for (int i = 0; i < 4; i++)
#pragma unroll
            for (int jd = 0; jd < 6; jd++) oacc[i][jd] *= al[i];
#pragma unroll 4
        for (int j = 0; j < 64; j++) {
            float p[4];
#pragma unroll
            for (int i = 0; i < 4; i++) p[i] = Ss[(ty*4 + i)*SD + j];
            float2 v0 = *(const float2*)(Vs + j*96 + tx*6);
            float2 v1 = *(const float2*)(Vs + j*96 + tx*6 + 2);
            float2 v2 = *(const float2*)(Vs + j*96 + tx*6 + 4);
            float v[6] = {v0.x, v0.y, v1.x, v1.y, v2.x, v2.y};
#pragma unroll
            for (int i = 0; i < 4; i++)
#pragma unroll
                for (int jd = 0; jd < 6; jd++)
                    oacc[i][jd] += p[i] * v[jd];
        }
        __syncthreads();
    }

#pragma unroll
    for (int i = 0; i < 4; i++) {
        int q = ty*4 + i;
        float inv_l = 1.f / lrow[q];
        float* orow = attn + (size_t)(b*S_ + q0 + q) * H_ + h*HD + tx*6;
        *(float2*)(orow)     = make_float2(oacc[i][0]*inv_l, oacc[i][1]*inv_l);
        *(float2*)(orow + 2) = make_float2(oacc[i][2]*inv_l, oacc[i][3]*inv_l);
        *(float2*)(orow + 4) = make_float2(oacc[i][4]*inv_l, oacc[i][5]*inv_l);
    }
}

// ---------------------------------------------------------------------------

extern "C" void kernel_launch(void* const* d_in, const int* in_sizes, int n_in,
                              void* d_out, int out_size)
{
    const float* hidden = (const float*)d_in[0];
    const float* w_qkv  = (const float*)d_in[2];
    const float* w_o    = (const float*)d_in[3];
    float* out = (float*)d_out;

    float *qkv, *attn;
    __nv_bfloat16 *h_hi, *h_lo, *wq_hi, *wq_lo, *wo_hi, *wo_lo, *a_hi, *a_lo;
    cudaGetSymbolAddress((void**)&qkv,   g_qkv);
    cudaGetSymbolAddress((void**)&attn,  g_attn);
    cudaGetSymbolAddress((void**)&h_hi,  g_h_hi);
    cudaGetSymbolAddress((void**)&h_lo,  g_h_lo);
    cudaGetSymbolAddress((void**)&wq_hi, g_wq_hi);
    cudaGetSymbolAddress((void**)&wq_lo, g_wq_lo);
    cudaGetSymbolAddress((void**)&wo_hi, g_wo_hi);
    cudaGetSymbolAddress((void**)&wo_lo, g_wo_lo);
    cudaGetSymbolAddress((void**)&a_hi,  g_a_hi);
    cudaGetSymbolAddress((void**)&a_lo,  g_a_lo);

    cudaFuncSetAttribute(gemm_3xbf16, cudaFuncAttributeMaxDynamicSharedMemorySize, GEMM_SMEM);

    // 1) split inputs/weights to bf16 hi/lo
    {
        int n4;
        n4 = (M_ * H_) / 4;
        split_f32<<<(n4 + 255)/256, 256>>>(hidden, h_hi, h_lo, n4);
        n4 = (QKV_W * H_) / 4;
        split_f32<<<(n4 + 255)/256, 256>>>(w_qkv, wq_hi, wq_lo, n4);
        n4 = (H_ * H_) / 4;
        split_f32<<<(n4 + 255)/256, 256>>>(w_o, wo_hi, wo_lo, n4);
    }

    // 2) QKV projection on tensor cores (HMMA): [4096,3072] x [4608,3072]^T
    gemm_3xbf16<<<dim3(QKV_W/128, M_/128), 256, GEMM_SMEM>>>(
        h_hi, h_lo, wq_hi, wq_lo, qkv, QKV_W, H_);

    // 3) RoPE in place
    {
        int total = B_ * S_ * (NH + NKV) * (HD/2);
        rope_kernel<<<(total + 255)/256, 256>>>(qkv);
    }

    // 4) causal GQA flash attention (fp32)
    {
        const int smem = (96*64*2 + 64*96 + 64*SD + 3*64) * (int)sizeof(float);
        cudaFuncSetAttribute(attn_kernel, cudaFuncAttributeMaxDynamicSharedMemorySize, smem);
        attn_kernel<<<dim3(S_/64, B_*NH), 256, smem>>>(qkv, attn);
    }

    // 5) split attention output, output projection
    {
        int n4 = (M_ * H_) / 4;
        split_f32<<<(n4 + 255)/256, 256>>>(attn, a_hi, a_lo, n4);
    }
    gemm_3xbf16<<<dim3(H_/128, M_/128), 256, GEMM_SMEM>>>(
        a_hi, a_lo, wo_hi, wo_lo, out, H_, H_);
}

// round 4
// speedup vs baseline: 2.7245x; 1.6383x over previous
#include <cuda_runtime.h>
#include <cuda_bf16.h>
#include <math.h>
#include <stdint.h>

#define B_   2
#define S_   2048
#define H_   3072
#define NH   32
#define NKV  8
#define HD   96
#define QKV_W (NH*HD + 2*NKV*HD)   // 4608
#define M_   (B_*S_)               // 4096

// ---------------- scratch (device globals: allocation-free rule) -----------
__device__ float g_qkv[(size_t)M_ * QKV_W];
__device__ __nv_bfloat16 g_h_hi[(size_t)M_ * H_],     g_h_lo[(size_t)M_ * H_];
__device__ __nv_bfloat16 g_wq_hi[(size_t)QKV_W * H_], g_wq_lo[(size_t)QKV_W * H_];
__device__ __nv_bfloat16 g_wo_hi[(size_t)H_ * H_],    g_wo_lo[(size_t)H_ * H_];
__device__ __nv_bfloat16 g_a_hi[(size_t)M_ * H_],     g_a_lo[(size_t)M_ * H_];
// head-major attention operand planes
__device__ __nv_bfloat16 g_q_hi[(size_t)B_*NH*S_*HD],  g_q_lo[(size_t)B_*NH*S_*HD];
__device__ __nv_bfloat16 g_k_hi[(size_t)B_*NKV*S_*HD], g_k_lo[(size_t)B_*NKV*S_*HD];
__device__ __nv_bfloat16 g_v_hi[(size_t)B_*NKV*S_*HD], g_v_lo[(size_t)B_*NKV*S_*HD];

// ---------------- base-target PTX helpers ----------------------------------
__device__ __forceinline__ void cp_async16(uint32_t dst, const void* src) {
    asm volatile("cp.async.cg.shared.global [%0], [%1], 16;"
                 :: "r"(dst), "l"(src) : "memory");
}
#define CP_COMMIT() asm volatile("cp.async.commit_group;" ::: "memory")
#define CP_WAIT(n)  asm volatile("cp.async.wait_group %0;" :: "n"(n) : "memory")

__device__ __forceinline__ void ldsm4(uint32_t& r0, uint32_t& r1, uint32_t& r2,
                                      uint32_t& r3, uint32_t addr) {
    asm volatile("ldmatrix.sync.aligned.m8n8.x4.shared.b16 {%0,%1,%2,%3}, [%4];"
                 : "=r"(r0), "=r"(r1), "=r"(r2), "=r"(r3) : "r"(addr));
}
__device__ __forceinline__ void ldsm4t(uint32_t& r0, uint32_t& r1, uint32_t& r2,
                                       uint32_t& r3, uint32_t addr) {
    asm volatile("ldmatrix.sync.aligned.m8n8.x4.trans.shared.b16 {%0,%1,%2,%3}, [%4];"
                 : "=r"(r0), "=r"(r1), "=r"(r2), "=r"(r3) : "r"(addr));
}
__device__ __forceinline__ void mma16816(float* c, uint32_t a0, uint32_t a1,
                                         uint32_t a2, uint32_t a3,
                                         uint32_t b0, uint32_t b1) {
    asm volatile(
        "mma.sync.aligned.m16n8k16.row.col.f32.bf16.bf16.f32 "
        "{%0,%1,%2,%3}, {%4,%5,%6,%7}, {%8,%9}, {%0,%1,%2,%3};"
        : "+f"(c[0]), "+f"(c[1]), "+f"(c[2]), "+f"(c[3])
        : "r"(a0), "r"(a1), "r"(a2), "r"(a3), "r"(b0), "r"(b1));
}

__device__ __forceinline__ uint32_t pack_bf16x2(float lo, float hi) {
    __nv_bfloat162 p = __floats2bfloat162_rn(lo, hi);   // .x=lo elem, .y=hi elem
    return *(uint32_t*)&p;
}

// ---------------------------------------------------------------------------
// fp32 -> (bf16 hi, bf16 lo) split
// ---------------------------------------------------------------------------
__global__ void split_f32(const float* __restrict__ x,
                          __nv_bfloat16* __restrict__ hi,
                          __nv_bfloat16* __restrict__ lo, int n4)
{
    int i = blockIdx.x * blockDim.x + threadIdx.x;
    if (i >= n4) return;
    float4 v = ((const float4*)x)[i];
    __nv_bfloat16 h0 = __float2bfloat16_rn(v.x);
    __nv_bfloat16 h1 = __float2bfloat16_rn(v.y);
    __nv_bfloat16 h2 = __float2bfloat16_rn(v.z);
    __nv_bfloat16 h3 = __float2bfloat16_rn(v.w);
    __nv_bfloat16 l0 = __float2bfloat16_rn(v.x - __bfloat162float(h0));
    __nv_bfloat16 l1 = __float2bfloat16_rn(v.y - __bfloat162float(h1));
    __nv_bfloat16 l2 = __float2bfloat16_rn(v.z - __bfloat162float(h2));
    __nv_bfloat16 l3 = __float2bfloat16_rn(v.w - __bfloat162float(h3));
    ((__nv_bfloat162*)hi)[2*i]   = __nv_bfloat162(h0, h1);
    ((__nv_bfloat162*)hi)[2*i+1] = __nv_bfloat162(h2, h3);
    ((__nv_bfloat162*)lo)[2*i]   = __nv_bfloat162(l0, l1);
    ((__nv_bfloat162*)lo)[2*i+1] = __nv_bfloat162(l2, l3);
}

// ---------------------------------------------------------------------------
// 3xBF16 mma.sync GEMM (NT), 128x128 CTA tile, BK=32, double-buffered.
// ---------------------------------------------------------------------------
#define BK      32
#define LDS_    40
#define PLANE_B (128 * LDS_ * 2)
#define BUF_B   (4 * PLANE_B)
#define GEMM_SMEM (2 * BUF_B)

__global__ __launch_bounds__(256, 1) void gemm_3xbf16(
    const __nv_bfloat16* __restrict__ Ahi, const __nv_bfloat16* __restrict__ Alo,
    const __nv_bfloat16* __restrict__ Bhi, const __nv_bfloat16* __restrict__ Blo,
    float* __restrict__ C, int N, int K)
{
    extern __shared__ __align__(128) char smc[];
    const uint32_t sbase = (uint32_t)__cvta_generic_to_shared(smc);
    const int tid  = threadIdx.x;
    const int warp = tid >> 5, lane = tid & 31;
    const int bm = blockIdx.y * 128, bn = blockIdx.x * 128;
    const int wm = (warp >> 2) * 64;
    const int wn = (warp & 3) * 32;

    const __nv_bfloat16* srcs[4] = {
        Ahi + (size_t)bm * K, Alo + (size_t)bm * K,
        Bhi + (size_t)bn * K, Blo + (size_t)bn * K };

    const int nch = K / BK;

    auto load_chunk = [&](int kc, int bb) {
        uint32_t sb = sbase + bb * BUF_B;
        #pragma unroll
        for (int p = 0; p < 4; p++) {
            const __nv_bfloat16* sp = srcs[p] + kc * BK;
            uint32_t pb = sb + p * PLANE_B;
            #pragma unroll
            for (int t = 0; t < 2; t++) {
                int f = tid + t * 256;
                int r = f >> 2, j = f & 3;
                cp_async16(pb + r * (LDS_ * 2) + j * 16,
                           sp + (size_t)r * K + j * 8);
            }
        }
        CP_COMMIT();
    };

    float c[4][4][4];
    #pragma unroll
    for (int i = 0; i < 4; i++)
        #pragma unroll
        for (int j = 0; j < 4; j++)
            #pragma unroll
            for (int q = 0; q < 4; q++) c[i][j][q] = 0.f;

    load_chunk(0, 0);

    const int arow = lane & 15;
    const int ak8  = (lane >> 4) * 8;
    const int brow = (lane & 7) + ((lane >> 4) << 3);
    const int bk8  = ((lane >> 3) & 1) * 8;

    #pragma unroll 1
    for (int kc = 0; kc < nch; kc++) {
        const int bb = kc & 1;
        if (kc + 1 < nch) { load_chunk(kc + 1, (kc + 1) & 1); CP_WAIT(1); }
        else              { CP_WAIT(0); }
        __syncthreads();

        const uint32_t sAh = sbase + bb * BUF_B;
        const uint32_t sAl = sAh + PLANE_B;
        const uint32_t sBh = sAh + 2 * PLANE_B;
        const uint32_t sBl = sAh + 3 * PLANE_B;

        #pragma unroll
        for (int ks = 0; ks < 2; ks++) {
            const int k0 = ks * 16;
            uint32_t ah[4][4], al[4][4], bh[4][2], bl[4][2];
            #pragma unroll
            for (int ti = 0; ti < 4; ti++) {
                uint32_t off = (uint32_t)((wm + ti*16 + arow) * LDS_ + k0 + ak8) * 2;
                ldsm4(ah[ti][0], ah[ti][1], ah[ti][2], ah[ti][3], sAh + off);
                ldsm4(al[ti][0], al[ti][1], al[ti][2], al[ti][3], sAl + off);
            }
            #pragma unroll
            for (int tp = 0; tp < 2; tp++) {
                uint32_t off = (uint32_t)((wn + tp*16 + brow) * LDS_ + k0 + bk8) * 2;
                ldsm4(bh[tp*2][0], bh[tp*2][1], bh[tp*2+1][0], bh[tp*2+1][1], sBh + off);
                ldsm4(bl[tp*2][0], bl[tp*2][1], bl[tp*2+1][0], bl[tp*2+1][1], sBl + off);
            }
            #pragma unroll
            for (int ti = 0; ti < 4; ti++)
                #pragma unroll
                for (int tj = 0; tj < 4; tj++) {
                    mma16816(c[ti][tj], ah[ti][0], ah[ti][1], ah[ti][2], ah[ti][3],
                             bh[tj][0], bh[tj][1]);
                    mma16816(c[ti][tj], ah[ti][0], ah[ti][1], ah[ti][2], ah[ti][3],
                             bl[tj][0], bl[tj][1]);
                    mma16816(c[ti][tj], al[ti][0], al[ti][1], al[ti][2], al[ti][3],
                             bh[tj][0], bh[tj][1]);
                }
        }
        __syncthreads();
    }

    const int cr = lane >> 2, cc = (lane & 3) * 2;
    #pragma unroll
    for (int ti = 0; ti < 4; ti++) {
        #pragma unroll
        for (int tj = 0; tj < 4; tj++) {
            int r0 = bm + wm + ti*16 + cr;
            int col = bn + wn + tj*8 + cc;
            *(float2*)(C + (size_t)r0 * N + col)       = make_float2(c[ti][tj][0], c[ti][tj][1]);
            *(float2*)(C + (size_t)(r0 + 8) * N + col) = make_float2(c[ti][tj][2], c[ti][tj][3]);
        }
    }
}

// ---------------------------------------------------------------------------
// RoPE + hi/lo split into head-major planes. Q gets the softmax scale folded in.
// positions = arange(S).
// ---------------------------------------------------------------------------
__global__ void rope_split(const float* __restrict__ qkv,
                           __nv_bfloat16* __restrict__ qhi, __nv_bfloat16* __restrict__ qlo,
                           __nv_bfloat16* __restrict__ khi, __nv_bfloat16* __restrict__ klo)
{
    const int total = B_ * S_ * (NH + NKV) * (HD / 2);
    int i = blockIdx.x * blockDim.x + threadIdx.x;
    if (i >= total) return;
    int d    = i % (HD/2);
    int t    = i / (HD/2);
    int head = t % (NH + NKV);
    int bs   = t / (NH + NKV);
    int b    = bs / S_;
    int s    = bs % S_;

    float inv = expf(-(float)d * (logf(10000.0f) / 48.0f));
    float ang = (float)s * inv;
    float sn, cs;
    sincosf(ang, &sn, &cs);

    const float* base = qkv + (size_t)bs * QKV_W + head * HD;
    float x1 = base[d];
    float x2 = base[d + 48];
    float y1 = x1 * cs - x2 * sn;
    float y2 = x2 * cs + x1 * sn;

    __nv_bfloat16 *hi, *lo;
    size_t idx;
    if (head < NH) {
        const float scale = 0.10206207261596577f;   // 1/sqrt(96) folded into Q
        y1 *= scale; y2 *= scale;
        idx = ((size_t)(b * NH + head) * S_ + s) * HD;
        hi = qhi; lo = qlo;
    } else {
        idx = ((size_t)(b * NKV + (head - NH)) * S_ + s) * HD;
        hi = khi; lo = klo;
    }
    __nv_bfloat16 h1 = __float2bfloat16_rn(y1);
    __nv_bfloat16 h2 = __float2bfloat16_rn(y2);
    hi[idx + d]      = h1;
    hi[idx + d + 48] = h2;
    lo[idx + d]      = __float2bfloat16_rn(y1 - __bfloat162float(h1));
    lo[idx + d + 48] = __float2bfloat16_rn(y2 - __bfloat162float(h2));
}

// V: hi/lo split into head-major planes (no rope).
__global__ void v_split(const float* __restrict__ qkv,
                        __nv_bfloat16* __restrict__ vhi, __nv_bfloat16* __restrict__ vlo)
{
    const int total = B_ * S_ * NKV * (HD / 4);
    int i = blockIdx.x * blockDim.x + threadIdx.x;
    if (i >= total) return;
    int d4  = i % (HD/4);
    int t   = i / (HD/4);
    int kvh = t % NKV;
    int bs  = t / NKV;
    int b   = bs / S_;
    int s   = bs % S_;

    const float* src = qkv + (size_t)bs * QKV_W + NH*HD + NKV*HD + kvh*HD + d4*4;
    float4 v = *(const float4*)src;
    size_t idx = ((size_t)(b * NKV + kvh) * S_ + s) * HD + d4*4;
    __nv_bfloat16 h0 = __float2bfloat16_rn(v.x);
    __nv_bfloat16 h1 = __float2bfloat16_rn(v.y);
    __nv_bfloat16 h2 = __float2bfloat16_rn(v.z);
    __nv_bfloat16 h3 = __float2bfloat16_rn(v.w);
    *(__nv_bfloat162*)(vhi + idx)     = __nv_bfloat162(h0, h1);
    *(__nv_bfloat162*)(vhi + idx + 2) = __nv_bfloat162(h2, h3);
    *(__nv_bfloat162*)(vlo + idx) =
        __nv_bfloat162(__float2bfloat16_rn(v.x - __bfloat162float(h0)),
                       __float2bfloat16_rn(v.y - __bfloat162float(h1)));
    *(__nv_bfloat162*)(vlo + idx + 2) =
        __nv_bfloat162(__float2bfloat16_rn(v.z - __bfloat162float(h2)),
                       __float2bfloat16_rn(v.w - __bfloat162float(h3)));
}

// ---------------------------------------------------------------------------
// Flash attention on mma.sync (3xBF16). CTA: 128 queries x one (b,h).
// 8 warps x 16 rows. 64-key tiles, cp.async double buffer.
// Output written directly as bf16 hi/lo planes for the output GEMM.
// ---------------------------------------------------------------------------
#define ALDS   104                      // padded bf16 row stride
#define QBYTES (128 * ALDS * 2)         // 26624
#define KVTILE (64 * ALDS * 2)          // 13312
#define KVBUF  (4 * KVTILE)             // 53248
#define ATT_SMEM (2*QBYTES + 2*KVBUF)   // 159744

__global__ __launch_bounds__(256, 1) void attn_mma(
    const __nv_bfloat16* __restrict__ qhi, const __nv_bfloat16* __restrict__ qlo,
    const __nv_bfloat16* __restrict__ khi, const __nv_bfloat16* __restrict__ klo,
    const __nv_bfloat16* __restrict__ vhi, const __nv_bfloat16* __restrict__ vlo,
    __nv_bfloat16* __restrict__ ahi, __nv_bfloat16* __restrict__ alo)
{
    extern __shared__ __align__(128) char smc[];
    const uint32_t sb  = (uint32_t)__cvta_generic_to_shared(smc);
    const uint32_t sQh = sb, sQl = sb + QBYTES;
    const uint32_t sKV = sb + 2 * QBYTES;

    const int tid  = threadIdx.x;
    const int warp = tid >> 5, lane = tid & 31;
    const int qt = blockIdx.x;            // 0..15 (128-query tiles)
    const int bh = blockIdx.y;            // 0..63
    const int b  = bh >> 5, h = bh & 31, kvh = h >> 2;
    const int q0 = qt * 128;
    const int wm = warp * 16;

    const __nv_bfloat16* qsh = qhi + ((size_t)(b*NH + h) * S_ + q0) * HD;
    const __nv_bfloat16* qsl = qlo + ((size_t)(b*NH + h) * S_ + q0) * HD;
    const __nv_bfloat16* ksh = khi + (size_t)(b*NKV + kvh) * S_ * HD;
    const __nv_bfloat16* ksl = klo + (size_t)(b*NKV + kvh) * S_ * HD;
    const __nv_bfloat16* vsh = vhi + (size_t)(b*NKV + kvh) * S_ * HD;
    const __nv_bfloat16* vsl = vlo + (size_t)(b*NKV + kvh) * S_ * HD;

    // Q tile load: 128 rows x 12 16B chunks x 2 planes
    #pragma unroll
    for (int u = 0; u < 6; u++) {
        int f = tid + u * 256;            // 0..1535
        int r = f / 12, cidx = f % 12;
        cp_async16(sQh + r * (ALDS*2) + cidx * 16, qsh + (size_t)r * HD + cidx * 8);
        cp_async16(sQl + r * (ALDS*2) + cidx * 16, qsl + (size_t)r * HD + cidx * 8);
    }

    auto load_kv = [&](int kt, int bb) {
        uint32_t base = sKV + bb * KVBUF;
        int k0 = kt * 64;
        #pragma unroll
        for (int u = 0; u < 3; u++) {
            int f = tid + u * 256;        // 0..767
            int r = f / 12, cidx = f % 12;
            size_t g = (size_t)(k0 + r) * HD + cidx * 8;
            uint32_t o = r * (ALDS*2) + cidx * 16;
            cp_async16(base + 0*KVTILE + o, ksh + g);
            cp_async16(base + 1*KVTILE + o, ksl + g);
            cp_async16(base + 2*KVTILE + o, vsh + g);
            cp_async16(base + 3*KVTILE + o, vsl + g);
        }
        CP_COMMIT();
    };

    const int nkt = 2 * qt + 2;
    load_kv(0, 0);     // group also covers the Q loads above

    // fragment index helpers (validated in gemm_3xbf16)
    const int arow = lane & 15;
    const int ak8  = (lane >> 4) * 8;
    const int brow = (lane & 7) + ((lane >> 4) << 3);
    const int bk8  = ((lane >> 3) & 1) * 8;
    const int vrow = lane & 15;
    const int vn8  = (lane >> 4) * 8;
    const int r_   = lane >> 2;            // accum row within 16
    const int c2_  = (lane & 3) * 2;       // accum col pair base

    float o[12][4];
    #pragma unroll
    for (int t = 0; t < 12; t++)
        #pragma unroll
        for (int q = 0; q < 4; q++) o[t][q] = 0.f;
    float m0 = -1e30f, m1 = -1e30f, l0 = 0.f, l1 = 0.f;

    const int row_g0 = q0 + wm + r_;       // global row for accum row r_
    const int wmax   = q0 + wm + 15;       // warp's max query row

    #pragma unroll 1
    for (int kt = 0; kt < nkt; kt++) {
        const int bb = kt & 1;
        const int k0 = kt * 64;
        if (kt + 1 < nkt) { load_kv(kt + 1, bb ^ 1); CP_WAIT(1); }
        else              { CP_WAIT(0); }
        __syncthreads();

        if (k0 <= wmax) {
            const uint32_t sKh = sKV + bb * KVBUF;
            const uint32_t sKl = sKh + KVTILE;
            const uint32_t sVh = sKh + 2 * KVTILE;
            const uint32_t sVl = sKh + 3 * KVTILE;

            // ---- scores: S = Q K^T (scale pre-folded into Q) ----
            float s[8][4];
            #pragma unroll
            for (int t = 0; t < 8; t++)
                #pragma unroll
                for (int q = 0; q < 4; q++) s[t][q] = 0.f;

            #pragma unroll
            for (int ks = 0; ks < 6; ks++) {
                uint32_t aoff = (uint32_t)((wm + arow) * ALDS + ks*16 + ak8) * 2;
                uint32_t ah[4], al[4];
                ldsm4(ah[0], ah[1], ah[2], ah[3], sQh + aoff);
                ldsm4(al[0], al[1], al[2], al[3], sQl + aoff);
                #pragma unroll
                for (int np = 0; np < 4; np++) {
                    uint32_t boff = (uint32_t)((np*16 + brow) * ALDS + ks*16 + bk8) * 2;
                    uint32_t bh_[4], bl_[4];
                    ldsm4(bh_[0], bh_[1], bh_[2], bh_[3], sKh + boff);
                    ldsm4(bl_[0], bl_[1], bl_[2], bl_[3], sKl + boff);
                    mma16816(s[2*np],   ah[0],ah[1],ah[2],ah[3], bh_[0], bh_[1]);
                    mma16816(s[2*np],   ah[0],ah[1],ah[2],ah[3], bl_[0], bl_[1]);
                    mma16816(s[2*np],   al[0],al[1],al[2],al[3], bh_[0], bh_[1]);
                    mma16816(s[2*np+1], ah[0],ah[1],ah[2],ah[3], bh_[2], bh_[3]);
                    mma16816(s[2*np+1], ah[0],ah[1],ah[2],ah[3], bl_[2], bl_[3]);
                    mma16816(s[2*np+1], al[0],al[1],al[2],al[3], bh_[2], bh_[3]);
                }
            }

            // ---- causal mask ----
            if (k0 + 63 > q0 + wm) {
                #pragma unroll
                for (int t = 0; t < 8; t++) {
                    int col = k0 + t*8 + c2_;
                    if (col     > row_g0)     s[t][0] = -1e30f;
                    if (col + 1 > row_g0)     s[t][1] = -1e30f;
                    if (col     > row_g0 + 8) s[t][2] = -1e30f;
                    if (col + 1 > row_g0 + 8) s[t][3] = -1e30f;
                }
            }

            // ---- online softmax ----
            float mx0 = -1e30f, mx1 = -1e30f;
            #pragma unroll
            for (int t = 0; t < 8; t++) {
                mx0 = fmaxf(mx0, fmaxf(s[t][0], s[t][1]));
                mx1 = fmaxf(mx1, fmaxf(s[t][2], s[t][3]));
            }
            mx0 = fmaxf(mx0, __shfl_xor_sync(0xffffffff, mx0, 1));
            mx0 = fmaxf(mx0, __shfl_xor_sync(0xffffffff, mx0, 2));
            mx1 = fmaxf(mx1, __shfl_xor_sync(0xffffffff, mx1, 1));
            mx1 = fmaxf(mx1, __shfl_xor_sync(0xffffffff, mx1, 2));

            float mn0 = fmaxf(m0, mx0), mn1 = fmaxf(m1, mx1);
            float al0 = __expf(m0 - mn0), al1 = __expf(m1 - mn1);
            m0 = mn0; m1 = mn1;

            float sum0 = 0.f, sum1 = 0.f;
            #pragma unroll
            for (int t = 0; t < 8; t++) {
                s[t][0] = __expf(s[t][0] - m0);
                s[t][1] = __expf(s[t][1] - m0);
                s[t][2] = __expf(s[t][2] - m1);
                s[t][3] = __expf(s[t][3] - m1);
                sum0 += s[t][0] + s[t][1];
                sum1 += s[t][2] + s[t][3];
            }
            sum0 += __shfl_xor_sync(0xffffffff, sum0, 1);
            sum0 += __shfl_xor_sync(0xffffffff, sum0, 2);
            sum1 += __shfl_xor_sync(0xffffffff, sum1, 1);
            sum1 += __shfl_xor_sync(0xffffffff, sum1, 2);
            l0 = l0 * al0 + sum0;
            l1 = l1 * al1 + sum1;

            // rescale running output
            #pragma unroll
            for (int t = 0; t < 12; t++) {
                o[t][0] *= al0; o[t][1] *= al0;
                o[t][2] *= al1; o[t][3] *= al1;
            }

            // ---- O += P V  (P hi/lo from accum fragments) ----
            #pragma unroll
            for (int ks = 0; ks < 4; ks++) {
                const int j0 = 2*ks, j1 = 2*ks + 1;
                uint32_t ph[4], pl[4];
                ph[0] = pack_bf16x2(s[j0][0], s[j0][1]);
                ph[1] = pack_bf16x2(s[j0][2], s[j0][3]);
                ph[2] = pack_bf16x2(s[j1][0], s[j1][1]);
                ph[3] = pack_bf16x2(s[j1][2], s[j1][3]);
                {
                    __nv_bfloat162 t0 = *(__nv_bfloat162*)&ph[0];
                    __nv_bfloat162 t1 = *(__nv_bfloat162*)&ph[1];
                    __nv_bfloat162 t2 = *(__nv_bfloat162*)&ph[2];
                    __nv_bfloat162 t3 = *(__nv_bfloat162*)&ph[3];
                    pl[0] = pack_bf16x2(s[j0][0] - __bfloat162float(t0.x),
                                        s[j0][1] - __bfloat162float(t0.y));
                    pl[1] = pack_bf16x2(s[j0][2] - __bfloat162float(t1.x),
                                        s[j0][3] - __bfloat162float(t1.y));
                    pl[2] = pack_bf16x2(s[j1][0] - __bfloat162float(t2.x),
                                        s[j1][1] - __bfloat162float(t2.y));
                    pl[3] = pack_bf16x2(s[j1][2] - __bfloat162float(t3.x),
                                        s[j1][3] - __bfloat162float(t3.y));
                }
                #pragma unroll
                for (int np = 0; np < 6; np++) {
                    uint32_t voff = (uint32_t)((ks*16 + vrow) * ALDS + np*16 + vn8) * 2;
                    uint32_t vh_[4], vl_[4];
                    ldsm4t(vh_[0], vh_[1], vh_[2], vh_[3], sVh + voff);
                    ldsm4t(vl_[0], vl_[1], vl_[2], vl_[3], sVl + voff);
                    mma16816(o[2*np],   ph[0],ph[1],ph[2],ph[3], vh_[0], vh_[1]);
                    mma16816(o[2*np],   ph[0],ph[1],ph[2],ph[3], vl_[0], vl_[1]);
                    mma16816(o[2*np],   pl[0],pl[1],pl[2],pl[3], vh_[0], vh_[1]);
                    mma16816(o[2*np+1], ph[0],ph[1],ph[2],ph[3], vh_[2], vh_[3]);
                    mma16816(o[2*np+1], ph[0],ph[1],ph[2],ph[3], vl_[2], vl_[3]);
                    mma16816(o[2*np+1], pl[0],pl[1],pl[2],pl[3], vh_[2], vh_[3]);
                }
            }
        }
        __syncthreads();
    }

    // ---- epilogue: normalize, split to bf16 hi/lo planes ----
    const float il0 = 1.f / l0, il1 = 1.f / l1;
    const size_t mrow0 = (size_t)(b * S_ + row_g0) * H_;
    const size_t mrow1 = mrow0 + 8 * (size_t)H_;
    #pragma unroll
    for (int t = 0; t < 12; t++) {
        int col = h * HD + t*8 + c2_;
        float v0 = o[t][0] * il0, v1 = o[t][1] * il0;
        float v2 = o[t][2] * il1, v3 = o[t][3] * il1;
        uint32_t h0 = pack_bf16x2(v0, v1);
        uint32_t h1 = pack_bf16x2(v2, v3);
        __nv_bfloat162 hh0 = *(__nv_bfloat162*)&h0;
        __nv_bfloat162 hh1 = *(__nv_bfloat162*)&h1;
        uint32_t l0p = pack_bf16x2(v0 - __bfloat162float(hh0.x),
                                   v1 - __bfloat162float(hh0.y));
        uint32_t l1p = pack_bf16x2(v2 - __bfloat162float(hh1.x),
                                   v3 - __bfloat162float(hh1.y));
        *(uint32_t*)(ahi + mrow0 + col) = h0;
        *(uint32_t*)(alo + mrow0 + col) = l0p;
        *(uint32_t*)(ahi + mrow1 + col) = h1;
        *(uint32_t*)(alo + mrow1 + col) = l1p;
    }
}

// ---------------------------------------------------------------------------

extern "C" void kernel_launch(void* const* d_in, const int* in_sizes, int n_in,
                              void* d_out, int out_size)
{
    const float* hidden = (const float*)d_in[0];
    const float* w_qkv  = (const float*)d_in[2];
    const float* w_o    = (const float*)d_in[3];
    float* out = (float*)d_out;

    float *qkv;
    __nv_bfloat16 *h_hi, *h_lo, *wq_hi, *wq_lo, *wo_hi, *wo_lo, *a_hi, *a_lo;
    __nv_bfloat16 *q_hi, *q_lo, *k_hi, *k_lo, *v_hi, *v_lo;
    cudaGetSymbolAddress((void**)&qkv,   g_qkv);
    cudaGetSymbolAddress((void**)&h_hi,  g_h_hi);
    cudaGetSymbolAddress((void**)&h_lo,  g_h_lo);
    cudaGetSymbolAddress((void**)&wq_hi, g_wq_hi);
    cudaGetSymbolAddress((void**)&wq_lo, g_wq_lo);
    cudaGetSymbolAddress((void**)&wo_hi, g_wo_hi);
    cudaGetSymbolAddress((void**)&wo_lo, g_wo_lo);
    cudaGetSymbolAddress((void**)&a_hi,  g_a_hi);
    cudaGetSymbolAddress((void**)&a_lo,  g_a_lo);
    cudaGetSymbolAddress((void**)&q_hi,  g_q_hi);
    cudaGetSymbolAddress((void**)&q_lo,  g_q_lo);
    cudaGetSymbolAddress((void**)&k_hi,  g_k_hi);
    cudaGetSymbolAddress((void**)&k_lo,  g_k_lo);
    cudaGetSymbolAddress((void**)&v_hi,  g_v_hi);
    cudaGetSymbolAddress((void**)&v_lo,  g_v_lo);

    cudaFuncSetAttribute(gemm_3xbf16, cudaFuncAttributeMaxDynamicSharedMemorySize, GEMM_SMEM);
    cudaFuncSetAttribute(attn_mma,    cudaFuncAttributeMaxDynamicSharedMemorySize, ATT_SMEM);

    // 1) split inputs/weights to bf16 hi/lo
    {
        int n4;
        n4 = (M_ * H_) / 4;
        split_f32<<<(n4 + 255)/256, 256>>>(hidden, h_hi, h_lo, n4);
        n4 = (QKV_W * H_) / 4;
        split_f32<<<(n4 + 255)/256, 256>>>(w_qkv, wq_hi, wq_lo, n4);
        n4 = (H_ * H_) / 4;
        split_f32<<<(n4 + 255)/256, 256>>>(w_o, wo_hi, wo_lo, n4);
    }

    // 2) QKV projection (HMMA 3xBF16)
    gemm_3xbf16<<<dim3(QKV_W/128, M_/128), 256, GEMM_SMEM>>>(
        h_hi, h_lo, wq_hi, wq_lo, qkv, QKV_W, H_);

    // 3) RoPE + split to head-major bf16 planes; V split
    {
        int total = B_ * S_ * (NH + NKV) * (HD/2);
        rope_split<<<(total + 255)/256, 256>>>(qkv, q_hi, q_lo, k_hi, k_lo);
        int vt = B_ * S_ * NKV * (HD/4);
        v_split<<<(vt + 255)/256, 256>>>(qkv, v_hi, v_lo);
    }

    // 4) causal GQA flash attention (HMMA 3xBF16), writes a_hi/a_lo directly
    attn_mma<<<dim3(S_/128, B_*NH), 256, ATT_SMEM>>>(
        q_hi, q_lo, k_hi, k_lo, v_hi, v_lo, a_hi, a_lo);

    // 5) output projection (HMMA 3xBF16)
    gemm_3xbf16<<<dim3(H_/128, M_/128), 256, GEMM_SMEM>>>(
        a_hi, a_lo, wo_hi, wo_lo, out, H_, H_);
}